// round 14
// baseline (speedup 1.0000x reference)
#include <cuda_runtime.h>
#include <cuda_bf16.h>
#include <math.h>

#define BATCH 8
#define SEQ   1024
#define CH    768
#define NH    12
#define HD    64
#define BHNUM (BATCH*NH)          // 96
#define MROWS (BATCH*SEQ)         // 8192
#define KP16  24                  // smem pitch (bf16) for KC=16 pipelined tiles
#define KP    40                  // smem pitch for KC=32 tiles (k_ctx)

typedef __nv_bfloat16  bf16;
typedef __nv_bfloat162 bf162;

// ---- persistent scratch (__device__ globals; no runtime allocation) ----
__device__ bf16 g_x_h[MROWS*CH],      g_x_l[MROWS*CH];
__device__ bf16 g_q_h[BHNUM*SEQ*HD],  g_q_l[BHNUM*SEQ*HD];    // pre-scaled by 0.125
__device__ bf16 g_k_h[BHNUM*SEQ*HD],  g_k_l[BHNUM*SEQ*HD];
__device__ bf16 g_vt_h[BHNUM*HD*SEQ], g_vt_l[BHNUM*HD*SEQ];   // [bh][d][seq]
__device__ bf16 g_ctx_h[MROWS*CH],    g_ctx_l[MROWS*CH];
__device__ bf16 g_wq_h[3*CH*CH],      g_wq_l[3*CH*CH];        // [n][k]
__device__ bf16 g_wp_h[CH*CH],        g_wp_l[CH*CH];          // [n][k]
__device__ float g_pmax[BHNUM*8*SEQ], g_psum[BHNUM*8*SEQ];    // per col-block stats
__device__ float g_rowm[BHNUM*SEQ],   g_rowinv[BHNUM*SEQ];

// ---- helpers ----
__device__ __forceinline__ void bsplit(float v, bf16& h, bf16& l) {
    h = __float2bfloat16(v);
    l = __float2bfloat16(v - __bfloat162float(h));
}
__device__ __forceinline__ void bsplit2(float x, float y, bf162& h, bf162& l) {
    h.x = __float2bfloat16(x); l.x = __float2bfloat16(x - __bfloat162float(h.x));
    h.y = __float2bfloat16(y); l.y = __float2bfloat16(y - __bfloat162float(h.y));
}
__device__ __forceinline__ void mma_bf16(float* c, unsigned a0, unsigned a1,
                                         unsigned a2, unsigned a3,
                                         unsigned b0, unsigned b1) {
    asm volatile(
        "mma.sync.aligned.m16n8k16.row.col.f32.bf16.bf16.f32 "
        "{%0,%1,%2,%3}, {%4,%5,%6,%7}, {%8,%9}, {%0,%1,%2,%3};\n"
        : "+f"(c[0]), "+f"(c[1]), "+f"(c[2]), "+f"(c[3])
        : "r"(a0), "r"(a1), "r"(a2), "r"(a3), "r"(b0), "r"(b1));
}
__device__ __forceinline__ unsigned sm_u32(const void* p) {
    return (unsigned)__cvta_generic_to_shared(p);
}
__device__ __forceinline__ void ldsm4(unsigned& r0, unsigned& r1,
                                      unsigned& r2, unsigned& r3, unsigned a) {
    asm volatile("ldmatrix.sync.aligned.m8n8.x4.shared.b16 {%0,%1,%2,%3}, [%4];\n"
                 : "=r"(r0), "=r"(r1), "=r"(r2), "=r"(r3) : "r"(a));
}
__device__ __forceinline__ void cpa16(unsigned s, const void* g) {
    asm volatile("cp.async.ca.shared.global [%0], [%1], 16;\n" :: "r"(s), "l"(g) : "memory");
}
__device__ __forceinline__ void cp_commit() {
    asm volatile("cp.async.commit_group;\n" ::: "memory");
}
__device__ __forceinline__ void cp_wait1() {
    asm volatile("cp.async.wait_group 1;\n" ::: "memory");
}
__device__ __forceinline__ void cp_wait0() {
    asm volatile("cp.async.wait_group 0;\n" ::: "memory");
}

// ---- split-bf16 MMA over MT x NT warp tile, fragments via ldmatrix.x4 ----
// A tiles: [row][PITCH] k-contiguous; B tiles: [n][PITCH] k-contiguous.
// A addr: lanes 0-7 rows m..m+7 @k, 8-15 rows +8 @k, 16-23 rows @k+8, 24-31 +8@k+8
// B addr: lanes 0-7 n..n+7 @k, 8-15 same n @k+8, 16-23 n+8.. @k, 24-31 n+8 @k+8
template<int PITCH, int MT, int NT>
__device__ __forceinline__ void mma_tile(const bf16* __restrict__ Ah,
                                         const bf16* __restrict__ Al,
                                         const bf16* __restrict__ Bh,
                                         const bf16* __restrict__ Bl,
                                         int mbase, int nbase, int kk,
                                         int lane, float (&c)[MT][NT][4]) {
    const int sub = lane >> 3, ri = lane & 7;
    const int aoff = (mbase + ri + (sub & 1) * 8) * PITCH + kk + (sub >> 1) * 8;
    const int boff = (nbase + (sub >> 1) * 8 + ri) * PITCH + kk + (sub & 1) * 8;

    unsigned bhf[NT][2], blf[NT][2];
    #pragma unroll
    for (int np = 0; np < NT/2; np++) {
        ldsm4(bhf[2*np][0], bhf[2*np][1], bhf[2*np+1][0], bhf[2*np+1][1],
              sm_u32(&Bh[boff + np*16*PITCH]));
        ldsm4(blf[2*np][0], blf[2*np][1], blf[2*np+1][0], blf[2*np+1][1],
              sm_u32(&Bl[boff + np*16*PITCH]));
    }
    #pragma unroll
    for (int mt = 0; mt < MT; mt++) {
        unsigned a0h, a1h, a2h, a3h, a0l, a1l, a2l, a3l;
        ldsm4(a0h, a1h, a2h, a3h, sm_u32(&Ah[aoff + mt*16*PITCH]));
        ldsm4(a0l, a1l, a2l, a3l, sm_u32(&Al[aoff + mt*16*PITCH]));
        #pragma unroll
        for (int nt = 0; nt < NT; nt++) {
            mma_bf16(c[mt][nt], a0h, a1h, a2h, a3h, bhf[nt][0], bhf[nt][1]);
            mma_bf16(c[mt][nt], a0h, a1h, a2h, a3h, blf[nt][0], blf[nt][1]);
            mma_bf16(c[mt][nt], a0l, a1l, a2l, a3l, bhf[nt][0], bhf[nt][1]);
        }
    }
}

// ---------------------------------------------------------------------------
// Prep A: split x into bf16 hi/lo
// ---------------------------------------------------------------------------
__global__ __launch_bounds__(256) void k_tx(const float* __restrict__ X)
{
    int i = blockIdx.x * 256 + threadIdx.x;
    float4 v = ((const float4*)X)[i];
    bf162 ha, la, hb, lb;
    bsplit2(v.x, v.y, ha, la);
    bsplit2(v.z, v.w, hb, lb);
    ((bf162*)g_x_h)[2*i]   = ha;
    ((bf162*)g_x_h)[2*i+1] = hb;
    ((bf162*)g_x_l)[2*i]   = la;
    ((bf162*)g_x_l)[2*i+1] = lb;
}

// ---------------------------------------------------------------------------
// Prep B: transpose + split fp32 weight [K][N] -> bf16 hi/lo [N][K]
// ---------------------------------------------------------------------------
__global__ void k_tw(const float* __restrict__ W, bf16* __restrict__ Th,
                     bf16* __restrict__ Tl, int K, int N)
{
    __shared__ float t[32][33];
    int k0 = blockIdx.y * 32, n0 = blockIdx.x * 32;
    int tx = threadIdx.x, ty = threadIdx.y;
    #pragma unroll
    for (int i = 0; i < 32; i += 8)
        t[ty + i][tx] = W[(size_t)(k0 + ty + i) * N + n0 + tx];
    __syncthreads();
    #pragma unroll
    for (int i = 0; i < 32; i += 8) {
        float v = t[tx][ty + i];
        bf16 h, l; bsplit(v, h, l);
        size_t o = (size_t)(n0 + ty + i) * K + k0 + tx;
        Th[o] = h; Tl[o] = l;
    }
}

// ---------------------------------------------------------------------------
// K1: QKV GEMM, cp.async 2-stage pipelined, KC=16.
// Block 128x128, 8 warps, warp tile 64x32.
// ---------------------------------------------------------------------------
__global__ __launch_bounds__(256) void k_qkv()
{
    const int K = CH;
    const int m0 = blockIdx.y * 128, n0 = blockIdx.x * 128;

    __shared__ bf16 Ah[2][128*KP16], Al[2][128*KP16];
    __shared__ bf16 Bh[2][128*KP16], Bl[2][128*KP16];

    const int tid = threadIdx.x, lane = tid & 31, w = tid >> 5;
    const int g = lane >> 2, t4 = lane & 3;
    const int wm = w & 1, wn = w >> 1;
    const int lr = tid >> 1, ch = tid & 1;

    const bf16* Agh = g_x_h  + (size_t)(m0 + lr) * CH + ch*8;
    const bf16* Agl = g_x_l  + (size_t)(m0 + lr) * CH + ch*8;
    const bf16* Bgh = g_wq_h + (size_t)(n0 + lr) * K  + ch*8;
    const bf16* Bgl = g_wq_l + (size_t)(n0 + lr) * K  + ch*8;
    const int so = lr*KP16 + ch*8;

    float c[4][4][4];
    #pragma unroll
    for (int a = 0; a < 4; a++)
        #pragma unroll
        for (int b = 0; b < 4; b++)
            #pragma unroll
            for (int i = 0; i < 4; i++) c[a][b][i] = 0.f;

    #pragma unroll
    for (int s = 0; s < 2; s++) {
        cpa16(sm_u32(&Ah[s][so]), Agh + s*16);
        cpa16(sm_u32(&Al[s][so]), Agl + s*16);
        cpa16(sm_u32(&Bh[s][so]), Bgh + s*16);
        cpa16(sm_u32(&Bl[s][so]), Bgl + s*16);
        cp_commit();
    }

    const int NIT = K / 16;
    for (int i = 0; i < NIT; i++) {
        if (i == NIT - 1) cp_wait0(); else cp_wait1();
        __syncthreads();
        int s = i & 1;
        mma_tile<KP16,4,4>(Ah[s], Al[s], Bh[s], Bl[s], wm*64, wn*32, 0, lane, c);
        __syncthreads();
        if (i + 2 < NIT) {
            int k0 = (i + 2) * 16;
            cpa16(sm_u32(&Ah[s][so]), Agh + k0);
            cpa16(sm_u32(&Al[s][so]), Agl + k0);
            cpa16(sm_u32(&Bh[s][so]), Bgh + k0);
            cpa16(sm_u32(&Bl[s][so]), Bgl + k0);
            cp_commit();
        }
    }

    const int which = n0 / CH;
    const int cb = n0 - which * CH;
    bf16 *dh, *dl;
    if (which == 0)      { dh = g_q_h;  dl = g_q_l;  }
    else if (which == 1) { dh = g_k_h;  dl = g_k_l;  }
    else                 { dh = g_vt_h; dl = g_vt_l; }
    const bool isv = (which == 2);
    const float qs = (which == 0) ? 0.125f : 1.0f;   // fold 1/sqrt(64) into Q

    #pragma unroll
    for (int mt = 0; mt < 4; mt++)
        #pragma unroll
        for (int nt = 0; nt < 4; nt++) {
            int nloc = cb + wn*32 + nt*8 + 2*t4;
            int h = nloc >> 6, d0 = nloc & 63;
            #pragma unroll
            for (int i = 0; i < 4; i++) {
                int m = m0 + wm*64 + mt*16 + g + 8*(i >> 1);
                int d = d0 + (i & 1);
                int b = m >> 10, sq = m & 1023;
                bf16 hh, ll; bsplit(c[mt][nt][i] * qs, hh, ll);
                size_t idx = isv
                    ? ((size_t)((b*NH + h)*HD + d))*SEQ + sq
                    : ((size_t)((b*NH + h)*SEQ + sq))*HD + d;
                dh[idx] = hh; dl[idx] = ll;
            }
        }
}

// ---------------------------------------------------------------------------
// K2: scores (raw) + per-block softmax partials.  Pipelined, KC=16, K=64.
// ---------------------------------------------------------------------------
__global__ __launch_bounds__(256) void k_scores(float* __restrict__ attn)
{
    const int bh = blockIdx.z;
    const int nb = blockIdx.x;
    const int m0 = blockIdx.y * 128, n0 = nb * 128;

    __shared__ bf16 Ah[2][128*KP16], Al[2][128*KP16];
    __shared__ bf16 Bh[2][128*KP16], Bl[2][128*KP16];

    const int tid = threadIdx.x, lane = tid & 31, w = tid >> 5;
    const int g = lane >> 2, t4 = lane & 3;
    const int wm = w & 1, wn = w >> 1;
    const int lr = tid >> 1, ch = tid & 1;

    const bf16* Agh = g_q_h + ((size_t)bh*SEQ + m0 + lr) * HD + ch*8;
    const bf16* Agl = g_q_l + ((size_t)bh*SEQ + m0 + lr) * HD + ch*8;
    const bf16* Bgh = g_k_h + ((size_t)bh*SEQ + n0 + lr) * HD + ch*8;
    const bf16* Bgl = g_k_l + ((size_t)bh*SEQ + n0 + lr) * HD + ch*8;
    const int so = lr*KP16 + ch*8;

    float c[4][4][4];
    #pragma unroll
    for (int a = 0; a < 4; a++)
        #pragma unroll
        for (int b = 0; b < 4; b++)
            #pragma unroll
            for (int i = 0; i < 4; i++) c[a][b][i] = 0.f;

    #pragma unroll
    for (int s = 0; s < 2; s++) {
        cpa16(sm_u32(&Ah[s][so]), Agh + s*16);
        cpa16(sm_u32(&Al[s][so]), Agl + s*16);
        cpa16(sm_u32(&Bh[s][so]), Bgh + s*16);
        cpa16(sm_u32(&Bl[s][so]), Bgl + s*16);
        cp_commit();
    }

    #pragma unroll
    for (int i = 0; i < 4; i++) {
        if (i == 3) cp_wait0(); else cp_wait1();
        __syncthreads();
        int s = i & 1;
        mma_tile<KP16,4,4>(Ah[s], Al[s], Bh[s], Bl[s], wm*64, wn*32, 0, lane, c);
        __syncthreads();
        if (i + 2 < 4) {
            int k0 = (i + 2) * 16;
            cpa16(sm_u32(&Ah[s][so]), Agh + k0);
            cpa16(sm_u32(&Al[s][so]), Agl + k0);
            cpa16(sm_u32(&Bh[s][so]), Bgh + k0);
            cpa16(sm_u32(&Bl[s][so]), Bgl + k0);
            cp_commit();
        }
    }

    // raw S write (Q pre-scaled, so c is already scores)
    float* C = attn + (size_t)bh * SEQ * SEQ;
    #pragma unroll
    for (int mt = 0; mt < 4; mt++)
        #pragma unroll
        for (int nt = 0; nt < 4; nt++) {
            int n = n0 + wn*32 + nt*8 + 2*t4;
            int m = m0 + wm*64 + mt*16 + g;
            *(float2*)&C[(size_t)m * SEQ + n]       = make_float2(c[mt][nt][0], c[mt][nt][1]);
            *(float2*)&C[(size_t)(m + 8) * SEQ + n] = make_float2(c[mt][nt][2], c[mt][nt][3]);
        }

    // ---- per-block softmax partials (smem aliased onto Ah; MMAs all done) ----
    float* pm = (float*)&Ah[0][0];      // [128][4]
    float* bm = pm + 512;               // [128]
    float* ps = bm + 128;               // [128][4]

    #pragma unroll
    for (int mt = 0; mt < 4; mt++) {
        float v0 = -1e30f, v1 = -1e30f;
        #pragma unroll
        for (int nt = 0; nt < 4; nt++) {
            v0 = fmaxf(v0, fmaxf(c[mt][nt][0], c[mt][nt][1]));
            v1 = fmaxf(v1, fmaxf(c[mt][nt][2], c[mt][nt][3]));
        }
        #pragma unroll
        for (int o = 1; o <= 2; o <<= 1) {
            v0 = fmaxf(v0, __shfl_xor_sync(0xffffffffu, v0, o));
            v1 = fmaxf(v1, __shfl_xor_sync(0xffffffffu, v1, o));
        }
        if (t4 == 0) {
            int r = wm*64 + mt*16 + g;
            pm[r*4 + wn] = v0;
            pm[(r + 8)*4 + wn] = v1;
        }
    }
    __syncthreads();
    if (tid < 128) {
        float m = pm[tid*4];
        #pragma unroll
        for (int i = 1; i < 4; i++) m = fmaxf(m, pm[tid*4 + i]);
        bm[tid] = m;
    }
    __syncthreads();
    #pragma unroll
    for (int mt = 0; mt < 4; mt++) {
        int r = wm*64 + mt*16 + g;
        float m0v = bm[r], m1v = bm[r + 8];
        float s0 = 0.f, s1 = 0.f;
        #pragma unroll
        for (int nt = 0; nt < 4; nt++) {
            s0 += __expf(c[mt][nt][0] - m0v) + __expf(c[mt][nt][1] - m0v);
            s1 += __expf(c[mt][nt][2] - m1v) + __expf(c[mt][nt][3] - m1v);
        }
        #pragma unroll
        for (int o = 1; o <= 2; o <<= 1) {
            s0 += __shfl_xor_sync(0xffffffffu, s0, o);
            s1 += __shfl_xor_sync(0xffffffffu, s1, o);
        }
        if (t4 == 0) {
            ps[r*4 + wn] = s0;
            ps[(r + 8)*4 + wn] = s1;
        }
    }
    __syncthreads();
    if (tid < 128) {
        float s = ps[tid*4] + ps[tid*4+1] + ps[tid*4+2] + ps[tid*4+3];
        size_t o = ((size_t)bh*8 + nb) * SEQ + m0 + tid;
        g_pmax[o] = bm[tid];
        g_psum[o] = s;
    }
}

// ---------------------------------------------------------------------------
// K3: reduce partials -> per-row (max, 1/sum)
// ---------------------------------------------------------------------------
__global__ __launch_bounds__(256) void k_red()
{
    int idx = blockIdx.x * 256 + threadIdx.x;       // bh*1024 + row
    int bh = idx >> 10, row = idx & 1023;
    float pm[8];
    float m = -1e30f;
    #pragma unroll
    for (int nb = 0; nb < 8; nb++) {
        pm[nb] = g_pmax[((size_t)bh*8 + nb) * SEQ + row];
        m = fmaxf(m, pm[nb]);
    }
    float tot = 0.f;
    #pragma unroll
    for (int nb = 0; nb < 8; nb++)
        tot += g_psum[((size_t)bh*8 + nb) * SEQ + row] * __expf(pm[nb] - m);
    g_rowm[idx]   = m;
    g_rowinv[idx] = 1.0f / tot;
}

// ---------------------------------------------------------------------------
// K4: ctx = softmax(S) @ V.  Reads raw S, normalizes on the fly, writes
// normalized P back to attn, accumulates ctx via split bf16 MMA (ldmatrix).
// Block 128x64, 8 warps (4x2), warp tile 32x32, KC=32.
// ---------------------------------------------------------------------------
__global__ __launch_bounds__(256) void k_ctx(float* __restrict__ attn)
{
    const int bh = blockIdx.y;
    const int b = bh / NH, h = bh - b * NH;
    const int m0 = blockIdx.x * 128;

    __shared__ bf16 Ah[128*KP], Al[128*KP], Bh[64*KP], Bl[64*KP];

    const int tid = threadIdx.x, lane = tid & 31, w = tid >> 5;
    const int g = lane >> 2, t4 = lane & 3;
    const int wm = w & 3, wn = w >> 2;
    const int lr = tid >> 1, lh = (tid & 1) * 16;
    const int vr = tid >> 2, vh = (tid & 3) * 8;

    float* A = attn + (size_t)bh * SEQ * SEQ;
    const bf16* vth = g_vt_h + (size_t)bh * HD * SEQ;
    const bf16* vtl = g_vt_l + (size_t)bh * HD * SEQ;

    const float mrow = g_rowm[(size_t)bh*SEQ + m0 + lr];
    const float irow = g_rowinv[(size_t)bh*SEQ + m0 + lr];

    float c[2][4][4];
    #pragma unroll
    for (int a = 0; a < 2; a++)
        #pragma unroll
        for (int n = 0; n < 4; n++)
            #pragma unroll
            for (int i = 0; i < 4; i++) c[a][n][i] = 0.f;

    for (int k0 = 0; k0 < SEQ; k0 += 32) {
        #pragma unroll
        for (int i = 0; i < 4; i++) {
            size_t ao = (size_t)(m0 + lr) * SEQ + k0 + lh + 4*i;
            float4 v = *(const float4*)&A[ao];
            v.x = __expf(v.x - mrow) * irow;
            v.y = __expf(v.y - mrow) * irow;
            v.z = __expf(v.z - mrow) * irow;
            v.w = __expf(v.w - mrow) * irow;
            *(float4*)&A[ao] = v;                       // normalized P out
            bf162 h2a, l2a, h2b, l2b;
            bsplit2(v.x, v.y, h2a, l2a);
            bsplit2(v.z, v.w, h2b, l2b);
            *(bf162*)&Ah[lr*KP + lh + 4*i    ] = h2a;
            *(bf162*)&Ah[lr*KP + lh + 4*i + 2] = h2b;
            *(bf162*)&Al[lr*KP + lh + 4*i    ] = l2a;
            *(bf162*)&Al[lr*KP + lh + 4*i + 2] = l2b;
        }
        *(uint4*)&Bh[vr*KP + vh] = *(const uint4*)&vth[(size_t)vr * SEQ + k0 + vh];
        *(uint4*)&Bl[vr*KP + vh] = *(const uint4*)&vtl[(size_t)vr * SEQ + k0 + vh];
        __syncthreads();

        mma_tile<KP,2,4>(Ah, Al, Bh, Bl, wm*32, wn*32, 0,  lane, c);
        mma_tile<KP,2,4>(Ah, Al, Bh, Bl, wm*32, wn*32, 16, lane, c);
        __syncthreads();
    }

    #pragma unroll
    for (int mt = 0; mt < 2; mt++)
        #pragma unroll
        for (int nt = 0; nt < 4; nt++) {
            int n = wn*32 + nt*8 + 2*t4;
            #pragma unroll
            for (int half = 0; half < 2; half++) {
                int m = m0 + wm*32 + mt*16 + g + 8*half;
                size_t row = (size_t)(b*SEQ + m) * CH + h*HD + n;
                bf162 hv, lv;
                bsplit2(c[mt][nt][2*half], c[mt][nt][2*half+1], hv, lv);
                *(bf162*)&g_ctx_h[row] = hv;
                *(bf162*)&g_ctx_l[row] = lv;
            }
        }
}

// ---------------------------------------------------------------------------
// K5: out = ctx @ w_proj + bias.  Pipelined, KC=16.
// ---------------------------------------------------------------------------
__global__ __launch_bounds__(256) void k_proj(const float* __restrict__ bias,
                                              float* __restrict__ out)
{
    const int K = CH;
    const int m0 = blockIdx.y * 128, n0 = blockIdx.x * 128;

    __shared__ bf16 Ah[2][128*KP16], Al[2][128*KP16];
    __shared__ bf16 Bh[2][128*KP16], Bl[2][128*KP16];

    const int tid = threadIdx.x, lane = tid & 31, w = tid >> 5;
    const int g = lane >> 2, t4 = lane & 3;
    const int wm = w & 1, wn = w >> 1;
    const int lr = tid >> 1, ch = tid & 1;

    const bf16* Agh = g_ctx_h + (size_t)(m0 + lr) * K + ch*8;
    const bf16* Agl = g_ctx_l + (size_t)(m0 + lr) * K + ch*8;
    const bf16* Bgh = g_wp_h  + (size_t)(n0 + lr) * K + ch*8;
    const bf16* Bgl = g_wp_l  + (size_t)(n0 + lr) * K + ch*8;
    const int so = lr*KP16 + ch*8;

    float c[4][4][4];
    #pragma unroll
    for (int a = 0; a < 4; a++)
        #pragma unroll
        for (int b2 = 0; b2 < 4; b2++)
            #pragma unroll
            for (int i = 0; i < 4; i++) c[a][b2][i] = 0.f;

    #pragma unroll
    for (int s = 0; s < 2; s++) {
        cpa16(sm_u32(&Ah[s][so]), Agh + s*16);
        cpa16(sm_u32(&Al[s][so]), Agl + s*16);
        cpa16(sm_u32(&Bh[s][so]), Bgh + s*16);
        cpa16(sm_u32(&Bl[s][so]), Bgl + s*16);
        cp_commit();
    }

    const int NIT = K / 16;
    for (int i = 0; i < NIT; i++) {
        if (i == NIT - 1) cp_wait0(); else cp_wait1();
        __syncthreads();
        int s = i & 1;
        mma_tile<KP16,4,4>(Ah[s], Al[s], Bh[s], Bl[s], wm*64, wn*32, 0, lane, c);
        __syncthreads();
        if (i + 2 < NIT) {
            int k0 = (i + 2) * 16;
            cpa16(sm_u32(&Ah[s][so]), Agh + k0);
            cpa16(sm_u32(&Al[s][so]), Agl + k0);
            cpa16(sm_u32(&Bh[s][so]), Bgh + k0);
            cpa16(sm_u32(&Bl[s][so]), Bgl + k0);
            cp_commit();
        }
    }

    #pragma unroll
    for (int mt = 0; mt < 4; mt++)
        #pragma unroll
        for (int nt = 0; nt < 4; nt++) {
            int n = n0 + wn*32 + nt*8 + 2*t4;
            float2 bi = *(const float2*)&bias[n];
            int m = m0 + wm*64 + mt*16 + g;
            *(float2*)&out[(size_t)m * CH + n] =
                make_float2(c[mt][nt][0] + bi.x, c[mt][nt][1] + bi.y);
            *(float2*)&out[(size_t)(m + 8) * CH + n] =
                make_float2(c[mt][nt][2] + bi.x, c[mt][nt][3] + bi.y);
        }
}

// ---------------------------------------------------------------------------
extern "C" void kernel_launch(void* const* d_in, const int* in_sizes, int n_in,
                              void* d_out, int out_size)
{
    const float* x      = (const float*)d_in[0];
    const float* w_qkv  = (const float*)d_in[1];
    const float* w_proj = (const float*)d_in[2];
    const float* b_proj = (const float*)d_in[3];

    float* out  = (float*)d_out;
    float* attn = out + (size_t)MROWS * CH;

    bf16 *wq_h, *wq_l, *wp_h, *wp_l;
    cudaGetSymbolAddress((void**)&wq_h, g_wq_h);
    cudaGetSymbolAddress((void**)&wq_l, g_wq_l);
    cudaGetSymbolAddress((void**)&wp_h, g_wp_h);
    cudaGetSymbolAddress((void**)&wp_l, g_wp_l);

    // 0. prep
    k_tx<<<MROWS*CH/1024, 256>>>(x);
    k_tw<<<dim3(3*CH/32, CH/32), dim3(32, 8)>>>(w_qkv, wq_h, wq_l, CH, 3*CH);
    k_tw<<<dim3(CH/32,   CH/32), dim3(32, 8)>>>(w_proj, wp_h, wp_l, CH, CH);

    // 1. QKV projection (pipelined)
    k_qkv<<<dim3(3*CH/128, MROWS/128), 256>>>();

    // 2. raw scores + softmax partials
    k_scores<<<dim3(SEQ/128, SEQ/128, BHNUM), 256>>>(attn);

    // 3. per-row softmax stats
    k_red<<<BHNUM*SEQ/256, 256>>>();

    // 4. normalize + P write + ctx = P@V
    k_ctx<<<dim3(SEQ/128, BHNUM), 256>>>(attn);

    // 5. output projection + bias (pipelined)
    k_proj<<<dim3(CH/128, MROWS/128), 256>>>(b_proj, out);
}

// round 15
// speedup vs baseline: 2.1913x; 2.1913x over previous
#include <cuda_runtime.h>
#include <cuda_bf16.h>
#include <math.h>

#define BATCH 8
#define SEQ   1024
#define CH    768
#define NH    12
#define HD    64
#define BHNUM (BATCH*NH)          // 96
#define MROWS (BATCH*SEQ)         // 8192
#define KP16  24                  // smem pitch (bf16) for KC=16 pipelined tiles
#define KP    40                  // smem pitch for KC=32 tiles (k_ctx)

typedef __nv_bfloat16  bf16;
typedef __nv_bfloat162 bf162;

// ---- persistent scratch (__device__ globals; no runtime allocation) ----
__device__ bf16 g_x_h[MROWS*CH],      g_x_l[MROWS*CH];
__device__ bf16 g_q_h[BHNUM*SEQ*HD],  g_q_l[BHNUM*SEQ*HD];    // pre-scaled by 0.125
__device__ bf16 g_k_h[BHNUM*SEQ*HD],  g_k_l[BHNUM*SEQ*HD];
__device__ bf16 g_vt_h[BHNUM*HD*SEQ], g_vt_l[BHNUM*HD*SEQ];   // [bh][d][seq]
__device__ bf16 g_ctx_h[MROWS*CH],    g_ctx_l[MROWS*CH];
__device__ bf16 g_wq_h[3*CH*CH],      g_wq_l[3*CH*CH];        // [n][k]
__device__ bf16 g_wp_h[CH*CH],        g_wp_l[CH*CH];          // [n][k]
__device__ float g_pmax[BHNUM*8*SEQ], g_psum[BHNUM*8*SEQ];    // per col-block stats
__device__ float g_rowm[BHNUM*SEQ],   g_rowinv[BHNUM*SEQ];

// ---- helpers ----
__device__ __forceinline__ void bsplit(float v, bf16& h, bf16& l) {
    h = __float2bfloat16(v);
    l = __float2bfloat16(v - __bfloat162float(h));
}
__device__ __forceinline__ void bsplit2(float x, float y, bf162& h, bf162& l) {
    h.x = __float2bfloat16(x); l.x = __float2bfloat16(x - __bfloat162float(h.x));
    h.y = __float2bfloat16(y); l.y = __float2bfloat16(y - __bfloat162float(h.y));
}
__device__ __forceinline__ void mma_bf16(float* c, unsigned a0, unsigned a1,
                                         unsigned a2, unsigned a3,
                                         unsigned b0, unsigned b1) {
    asm volatile(
        "mma.sync.aligned.m16n8k16.row.col.f32.bf16.bf16.f32 "
        "{%0,%1,%2,%3}, {%4,%5,%6,%7}, {%8,%9}, {%0,%1,%2,%3};\n"
        : "+f"(c[0]), "+f"(c[1]), "+f"(c[2]), "+f"(c[3])
        : "r"(a0), "r"(a1), "r"(a2), "r"(a3), "r"(b0), "r"(b1));
}
__device__ __forceinline__ unsigned sm_u32(const void* p) {
    return (unsigned)__cvta_generic_to_shared(p);
}
__device__ __forceinline__ void ldsm4(unsigned& r0, unsigned& r1,
                                      unsigned& r2, unsigned& r3, unsigned a) {
    asm volatile("ldmatrix.sync.aligned.m8n8.x4.shared.b16 {%0,%1,%2,%3}, [%4];\n"
                 : "=r"(r0), "=r"(r1), "=r"(r2), "=r"(r3) : "r"(a));
}
__device__ __forceinline__ void cpa16(unsigned s, const void* g) {
    asm volatile("cp.async.ca.shared.global [%0], [%1], 16;\n" :: "r"(s), "l"(g) : "memory");
}
__device__ __forceinline__ void cp_commit() {
    asm volatile("cp.async.commit_group;\n" ::: "memory");
}
__device__ __forceinline__ void cp_wait1() {
    asm volatile("cp.async.wait_group 1;\n" ::: "memory");
}
__device__ __forceinline__ void cp_wait0() {
    asm volatile("cp.async.wait_group 0;\n" ::: "memory");
}

// ---- split-bf16 MMA over MT x NT warp tile, fragments via ldmatrix.x4 ----
template<int PITCH, int MT, int NT>
__device__ __forceinline__ void mma_tile(const bf16* __restrict__ Ah,
                                         const bf16* __restrict__ Al,
                                         const bf16* __restrict__ Bh,
                                         const bf16* __restrict__ Bl,
                                         int mbase, int nbase, int kk,
                                         int lane, float (&c)[MT][NT][4]) {
    const int sub = lane >> 3, ri = lane & 7;
    const int aoff = (mbase + ri + (sub & 1) * 8) * PITCH + kk + (sub >> 1) * 8;
    const int boff = (nbase + (sub >> 1) * 8 + ri) * PITCH + kk + (sub & 1) * 8;

    unsigned bhf[NT][2], blf[NT][2];
    #pragma unroll
    for (int np = 0; np < NT/2; np++) {
        ldsm4(bhf[2*np][0], bhf[2*np][1], bhf[2*np+1][0], bhf[2*np+1][1],
              sm_u32(&Bh[boff + np*16*PITCH]));
        ldsm4(blf[2*np][0], blf[2*np][1], blf[2*np+1][0], blf[2*np+1][1],
              sm_u32(&Bl[boff + np*16*PITCH]));
    }
    #pragma unroll
    for (int mt = 0; mt < MT; mt++) {
        unsigned a0h, a1h, a2h, a3h, a0l, a1l, a2l, a3l;
        ldsm4(a0h, a1h, a2h, a3h, sm_u32(&Ah[aoff + mt*16*PITCH]));
        ldsm4(a0l, a1l, a2l, a3l, sm_u32(&Al[aoff + mt*16*PITCH]));
        #pragma unroll
        for (int nt = 0; nt < NT; nt++) {
            mma_bf16(c[mt][nt], a0h, a1h, a2h, a3h, bhf[nt][0], bhf[nt][1]);
            mma_bf16(c[mt][nt], a0h, a1h, a2h, a3h, blf[nt][0], blf[nt][1]);
            mma_bf16(c[mt][nt], a0l, a1l, a2l, a3l, bhf[nt][0], bhf[nt][1]);
        }
    }
}

// ---------------------------------------------------------------------------
// Prep A: split x into bf16 hi/lo
// ---------------------------------------------------------------------------
__global__ __launch_bounds__(256) void k_tx(const float* __restrict__ X)
{
    int i = blockIdx.x * 256 + threadIdx.x;
    float4 v = ((const float4*)X)[i];
    bf162 ha, la, hb, lb;
    bsplit2(v.x, v.y, ha, la);
    bsplit2(v.z, v.w, hb, lb);
    ((bf162*)g_x_h)[2*i]   = ha;
    ((bf162*)g_x_h)[2*i+1] = hb;
    ((bf162*)g_x_l)[2*i]   = la;
    ((bf162*)g_x_l)[2*i+1] = lb;
}

// ---------------------------------------------------------------------------
// Prep B: transpose + split fp32 weight [K][N] -> bf16 hi/lo [N][K]
// ---------------------------------------------------------------------------
__global__ void k_tw(const float* __restrict__ W, bf16* __restrict__ Th,
                     bf16* __restrict__ Tl, int K, int N)
{
    __shared__ float t[32][33];
    int k0 = blockIdx.y * 32, n0 = blockIdx.x * 32;
    int tx = threadIdx.x, ty = threadIdx.y;
    #pragma unroll
    for (int i = 0; i < 32; i += 8)
        t[ty + i][tx] = W[(size_t)(k0 + ty + i) * N + n0 + tx];
    __syncthreads();
    #pragma unroll
    for (int i = 0; i < 32; i += 8) {
        float v = t[tx][ty + i];
        bf16 h, l; bsplit(v, h, l);
        size_t o = (size_t)(n0 + ty + i) * K + k0 + tx;
        Th[o] = h; Tl[o] = l;
    }
}

// ---------------------------------------------------------------------------
// K1: QKV GEMM, cp.async 2-stage pipelined, KC=16.  2 CTAs/SM forced.
// ---------------------------------------------------------------------------
__global__ __launch_bounds__(256, 2) void k_qkv()
{
    const int K = CH;
    const int m0 = blockIdx.y * 128, n0 = blockIdx.x * 128;

    __shared__ bf16 Ah[2][128*KP16], Al[2][128*KP16];
    __shared__ bf16 Bh[2][128*KP16], Bl[2][128*KP16];

    const int tid = threadIdx.x, lane = tid & 31, w = tid >> 5;
    const int g = lane >> 2, t4 = lane & 3;
    const int wm = w & 1, wn = w >> 1;
    const int lr = tid >> 1, ch = tid & 1;

    const bf16* Agh = g_x_h  + (size_t)(m0 + lr) * CH + ch*8;
    const bf16* Agl = g_x_l  + (size_t)(m0 + lr) * CH + ch*8;
    const bf16* Bgh = g_wq_h + (size_t)(n0 + lr) * K  + ch*8;
    const bf16* Bgl = g_wq_l + (size_t)(n0 + lr) * K  + ch*8;
    const int so = lr*KP16 + ch*8;

    float c[4][4][4];
    #pragma unroll
    for (int a = 0; a < 4; a++)
        #pragma unroll
        for (int b = 0; b < 4; b++)
            #pragma unroll
            for (int i = 0; i < 4; i++) c[a][b][i] = 0.f;

    #pragma unroll
    for (int s = 0; s < 2; s++) {
        cpa16(sm_u32(&Ah[s][so]), Agh + s*16);
        cpa16(sm_u32(&Al[s][so]), Agl + s*16);
        cpa16(sm_u32(&Bh[s][so]), Bgh + s*16);
        cpa16(sm_u32(&Bl[s][so]), Bgl + s*16);
        cp_commit();
    }

    const int NIT = K / 16;
    for (int i = 0; i < NIT; i++) {
        if (i == NIT - 1) cp_wait0(); else cp_wait1();
        __syncthreads();
        int s = i & 1;
        mma_tile<KP16,4,4>(Ah[s], Al[s], Bh[s], Bl[s], wm*64, wn*32, 0, lane, c);
        __syncthreads();
        if (i + 2 < NIT) {
            int k0 = (i + 2) * 16;
            cpa16(sm_u32(&Ah[s][so]), Agh + k0);
            cpa16(sm_u32(&Al[s][so]), Agl + k0);
            cpa16(sm_u32(&Bh[s][so]), Bgh + k0);
            cpa16(sm_u32(&Bl[s][so]), Bgl + k0);
            cp_commit();
        }
    }

    const int which = n0 / CH;
    const int cb = n0 - which * CH;
    bf16 *dh, *dl;
    if (which == 0)      { dh = g_q_h;  dl = g_q_l;  }
    else if (which == 1) { dh = g_k_h;  dl = g_k_l;  }
    else                 { dh = g_vt_h; dl = g_vt_l; }
    const bool isv = (which == 2);
    const float qs = (which == 0) ? 0.125f : 1.0f;   // fold 1/sqrt(64) into Q

    #pragma unroll
    for (int mt = 0; mt < 4; mt++)
        #pragma unroll
        for (int nt = 0; nt < 4; nt++) {
            int nloc = cb + wn*32 + nt*8 + 2*t4;
            int h = nloc >> 6, d0 = nloc & 63;
            #pragma unroll
            for (int i = 0; i < 4; i++) {
                int m = m0 + wm*64 + mt*16 + g + 8*(i >> 1);
                int d = d0 + (i & 1);
                int b = m >> 10, sq = m & 1023;
                bf16 hh, ll; bsplit(c[mt][nt][i] * qs, hh, ll);
                size_t idx = isv
                    ? ((size_t)((b*NH + h)*HD + d))*SEQ + sq
                    : ((size_t)((b*NH + h)*SEQ + sq))*HD + d;
                dh[idx] = hh; dl[idx] = ll;
            }
        }
}

// ---------------------------------------------------------------------------
// K2: scores (raw) + per-block softmax partials.  Pipelined, KC=16, K=64.
// ---------------------------------------------------------------------------
__global__ __launch_bounds__(256, 2) void k_scores(float* __restrict__ attn)
{
    const int bh = blockIdx.z;
    const int nb = blockIdx.x;
    const int m0 = blockIdx.y * 128, n0 = nb * 128;

    __shared__ bf16 Ah[2][128*KP16], Al[2][128*KP16];
    __shared__ bf16 Bh[2][128*KP16], Bl[2][128*KP16];

    const int tid = threadIdx.x, lane = tid & 31, w = tid >> 5;
    const int g = lane >> 2, t4 = lane & 3;
    const int wm = w & 1, wn = w >> 1;
    const int lr = tid >> 1, ch = tid & 1;

    const bf16* Agh = g_q_h + ((size_t)bh*SEQ + m0 + lr) * HD + ch*8;
    const bf16* Agl = g_q_l + ((size_t)bh*SEQ + m0 + lr) * HD + ch*8;
    const bf16* Bgh = g_k_h + ((size_t)bh*SEQ + n0 + lr) * HD + ch*8;
    const bf16* Bgl = g_k_l + ((size_t)bh*SEQ + n0 + lr) * HD + ch*8;
    const int so = lr*KP16 + ch*8;

    float c[4][4][4];
    #pragma unroll
    for (int a = 0; a < 4; a++)
        #pragma unroll
        for (int b = 0; b < 4; b++)
            #pragma unroll
            for (int i = 0; i < 4; i++) c[a][b][i] = 0.f;

    #pragma unroll
    for (int s = 0; s < 2; s++) {
        cpa16(sm_u32(&Ah[s][so]), Agh + s*16);
        cpa16(sm_u32(&Al[s][so]), Agl + s*16);
        cpa16(sm_u32(&Bh[s][so]), Bgh + s*16);
        cpa16(sm_u32(&Bl[s][so]), Bgl + s*16);
        cp_commit();
    }

    #pragma unroll
    for (int i = 0; i < 4; i++) {
        if (i == 3) cp_wait0(); else cp_wait1();
        __syncthreads();
        int s = i & 1;
        mma_tile<KP16,4,4>(Ah[s], Al[s], Bh[s], Bl[s], wm*64, wn*32, 0, lane, c);
        __syncthreads();
        if (i + 2 < 4) {
            int k0 = (i + 2) * 16;
            cpa16(sm_u32(&Ah[s][so]), Agh + k0);
            cpa16(sm_u32(&Al[s][so]), Agl + k0);
            cpa16(sm_u32(&Bh[s][so]), Bgh + k0);
            cpa16(sm_u32(&Bl[s][so]), Bgl + k0);
            cp_commit();
        }
    }

    // raw S write (Q pre-scaled, so c is already scores)
    float* C = attn + (size_t)bh * SEQ * SEQ;
    #pragma unroll
    for (int mt = 0; mt < 4; mt++)
        #pragma unroll
        for (int nt = 0; nt < 4; nt++) {
            int n = n0 + wn*32 + nt*8 + 2*t4;
            int m = m0 + wm*64 + mt*16 + g;
            *(float2*)&C[(size_t)m * SEQ + n]       = make_float2(c[mt][nt][0], c[mt][nt][1]);
            *(float2*)&C[(size_t)(m + 8) * SEQ + n] = make_float2(c[mt][nt][2], c[mt][nt][3]);
        }

    // ---- per-block softmax partials (smem aliased onto Ah; MMAs all done) ----
    float* pm = (float*)&Ah[0][0];      // [128][4]
    float* bm = pm + 512;               // [128]
    float* ps = bm + 128;               // [128][4]

    #pragma unroll
    for (int mt = 0; mt < 4; mt++) {
        float v0 = -1e30f, v1 = -1e30f;
        #pragma unroll
        for (int nt = 0; nt < 4; nt++) {
            v0 = fmaxf(v0, fmaxf(c[mt][nt][0], c[mt][nt][1]));
            v1 = fmaxf(v1, fmaxf(c[mt][nt][2], c[mt][nt][3]));
        }
        #pragma unroll
        for (int o = 1; o <= 2; o <<= 1) {
            v0 = fmaxf(v0, __shfl_xor_sync(0xffffffffu, v0, o));
            v1 = fmaxf(v1, __shfl_xor_sync(0xffffffffu, v1, o));
        }
        if (t4 == 0) {
            int r = wm*64 + mt*16 + g;
            pm[r*4 + wn] = v0;
            pm[(r + 8)*4 + wn] = v1;
        }
    }
    __syncthreads();
    if (tid < 128) {
        float m = pm[tid*4];
        #pragma unroll
        for (int i = 1; i < 4; i++) m = fmaxf(m, pm[tid*4 + i]);
        bm[tid] = m;
    }
    __syncthreads();
    #pragma unroll
    for (int mt = 0; mt < 4; mt++) {
        int r = wm*64 + mt*16 + g;
        float m0v = bm[r], m1v = bm[r + 8];
        float s0 = 0.f, s1 = 0.f;
        #pragma unroll
        for (int nt = 0; nt < 4; nt++) {
            s0 += __expf(c[mt][nt][0] - m0v) + __expf(c[mt][nt][1] - m0v);
            s1 += __expf(c[mt][nt][2] - m1v) + __expf(c[mt][nt][3] - m1v);
        }
        #pragma unroll
        for (int o = 1; o <= 2; o <<= 1) {
            s0 += __shfl_xor_sync(0xffffffffu, s0, o);
            s1 += __shfl_xor_sync(0xffffffffu, s1, o);
        }
        if (t4 == 0) {
            ps[r*4 + wn] = s0;
            ps[(r + 8)*4 + wn] = s1;
        }
    }
    __syncthreads();
    if (tid < 128) {
        float s = ps[tid*4] + ps[tid*4+1] + ps[tid*4+2] + ps[tid*4+3];
        size_t o = ((size_t)bh*8 + nb) * SEQ + m0 + tid;
        g_pmax[o] = bm[tid];
        g_psum[o] = s;
    }
}

// ---------------------------------------------------------------------------
// K3: reduce partials -> per-row (max, 1/sum)
// ---------------------------------------------------------------------------
__global__ __launch_bounds__(256) void k_red()
{
    int idx = blockIdx.x * 256 + threadIdx.x;       // bh*1024 + row
    int bh = idx >> 10, row = idx & 1023;
    float pm[8];
    float m = -1e30f;
    #pragma unroll
    for (int nb = 0; nb < 8; nb++) {
        pm[nb] = g_pmax[((size_t)bh*8 + nb) * SEQ + row];
        m = fmaxf(m, pm[nb]);
    }
    float tot = 0.f;
    #pragma unroll
    for (int nb = 0; nb < 8; nb++)
        tot += g_psum[((size_t)bh*8 + nb) * SEQ + row] * __expf(pm[nb] - m);
    g_rowm[idx]   = m;
    g_rowinv[idx] = 1.0f / tot;
}

// ---------------------------------------------------------------------------
// K4: ctx = softmax(S) @ V.  Reads raw S, normalizes on the fly, writes
// normalized P back to attn, accumulates ctx via split bf16 MMA (ldmatrix).
// ---------------------------------------------------------------------------
__global__ __launch_bounds__(256, 2) void k_ctx(float* __restrict__ attn)
{
    const int bh = blockIdx.y;
    const int b = bh / NH, h = bh - b * NH;
    const int m0 = blockIdx.x * 128;

    __shared__ bf16 Ah[128*KP], Al[128*KP], Bh[64*KP], Bl[64*KP];

    const int tid = threadIdx.x, lane = tid & 31, w = tid >> 5;
    const int g = lane >> 2, t4 = lane & 3;
    const int wm = w & 3, wn = w >> 2;
    const int lr = tid >> 1, lh = (tid & 1) * 16;
    const int vr = tid >> 2, vh = (tid & 3) * 8;

    float* A = attn + (size_t)bh * SEQ * SEQ;
    const bf16* vth = g_vt_h + (size_t)bh * HD * SEQ;
    const bf16* vtl = g_vt_l + (size_t)bh * HD * SEQ;

    const float mrow = g_rowm[(size_t)bh*SEQ + m0 + lr];
    const float irow = g_rowinv[(size_t)bh*SEQ + m0 + lr];

    float c[2][4][4];
    #pragma unroll
    for (int a = 0; a < 2; a++)
        #pragma unroll
        for (int n = 0; n < 4; n++)
            #pragma unroll
            for (int i = 0; i < 4; i++) c[a][n][i] = 0.f;

    for (int k0 = 0; k0 < SEQ; k0 += 32) {
        #pragma unroll
        for (int i = 0; i < 4; i++) {
            size_t ao = (size_t)(m0 + lr) * SEQ + k0 + lh + 4*i;
            float4 v = *(const float4*)&A[ao];
            v.x = __expf(v.x - mrow) * irow;
            v.y = __expf(v.y - mrow) * irow;
            v.z = __expf(v.z - mrow) * irow;
            v.w = __expf(v.w - mrow) * irow;
            *(float4*)&A[ao] = v;                       // normalized P out
            bf162 h2a, l2a, h2b, l2b;
            bsplit2(v.x, v.y, h2a, l2a);
            bsplit2(v.z, v.w, h2b, l2b);
            *(bf162*)&Ah[lr*KP + lh + 4*i    ] = h2a;
            *(bf162*)&Ah[lr*KP + lh + 4*i + 2] = h2b;
            *(bf162*)&Al[lr*KP + lh + 4*i    ] = l2a;
            *(bf162*)&Al[lr*KP + lh + 4*i + 2] = l2b;
        }
        *(uint4*)&Bh[vr*KP + vh] = *(const uint4*)&vth[(size_t)vr * SEQ + k0 + vh];
        *(uint4*)&Bl[vr*KP + vh] = *(const uint4*)&vtl[(size_t)vr * SEQ + k0 + vh];
        __syncthreads();

        mma_tile<KP,2,4>(Ah, Al, Bh, Bl, wm*32, wn*32, 0,  lane, c);
        mma_tile<KP,2,4>(Ah, Al, Bh, Bl, wm*32, wn*32, 16, lane, c);
        __syncthreads();
    }

    #pragma unroll
    for (int mt = 0; mt < 2; mt++)
        #pragma unroll
        for (int nt = 0; nt < 4; nt++) {
            int n = wn*32 + nt*8 + 2*t4;
            #pragma unroll
            for (int half = 0; half < 2; half++) {
                int m = m0 + wm*32 + mt*16 + g + 8*half;
                size_t row = (size_t)(b*SEQ + m) * CH + h*HD + n;
                bf162 hv, lv;
                bsplit2(c[mt][nt][2*half], c[mt][nt][2*half+1], hv, lv);
                *(bf162*)&g_ctx_h[row] = hv;
                *(bf162*)&g_ctx_l[row] = lv;
            }
        }
}

// ---------------------------------------------------------------------------
// K5: out = ctx @ w_proj + bias.  Pipelined, KC=16.
// ---------------------------------------------------------------------------
__global__ __launch_bounds__(256, 2) void k_proj(const float* __restrict__ bias,
                                                 float* __restrict__ out)
{
    const int K = CH;
    const int m0 = blockIdx.y * 128, n0 = blockIdx.x * 128;

    __shared__ bf16 Ah[2][128*KP16], Al[2][128*KP16];
    __shared__ bf16 Bh[2][128*KP16], Bl[2][128*KP16];

    const int tid = threadIdx.x, lane = tid & 31, w = tid >> 5;
    const int g = lane >> 2, t4 = lane & 3;
    const int wm = w & 1, wn = w >> 1;
    const int lr = tid >> 1, ch = tid & 1;

    const bf16* Agh = g_ctx_h + (size_t)(m0 + lr) * K + ch*8;
    const bf16* Agl = g_ctx_l + (size_t)(m0 + lr) * K + ch*8;
    const bf16* Bgh = g_wp_h  + (size_t)(n0 + lr) * K + ch*8;
    const bf16* Bgl = g_wp_l  + (size_t)(n0 + lr) * K + ch*8;
    const int so = lr*KP16 + ch*8;

    float c[4][4][4];
    #pragma unroll
    for (int a = 0; a < 4; a++)
        #pragma unroll
        for (int b2 = 0; b2 < 4; b2++)
            #pragma unroll
            for (int i = 0; i < 4; i++) c[a][b2][i] = 0.f;

    #pragma unroll
    for (int s = 0; s < 2; s++) {
        cpa16(sm_u32(&Ah[s][so]), Agh + s*16);
        cpa16(sm_u32(&Al[s][so]), Agl + s*16);
        cpa16(sm_u32(&Bh[s][so]), Bgh + s*16);
        cpa16(sm_u32(&Bl[s][so]), Bgl + s*16);
        cp_commit();
    }

    const int NIT = K / 16;
    for (int i = 0; i < NIT; i++) {
        if (i == NIT - 1) cp_wait0(); else cp_wait1();
        __syncthreads();
        int s = i & 1;
        mma_tile<KP16,4,4>(Ah[s], Al[s], Bh[s], Bl[s], wm*64, wn*32, 0, lane, c);
        __syncthreads();
        if (i + 2 < NIT) {
            int k0 = (i + 2) * 16;
            cpa16(sm_u32(&Ah[s][so]), Agh + k0);
            cpa16(sm_u32(&Al[s][so]), Agl + k0);
            cpa16(sm_u32(&Bh[s][so]), Bgh + k0);
            cpa16(sm_u32(&Bl[s][so]), Bgl + k0);
            cp_commit();
        }
    }

    #pragma unroll
    for (int mt = 0; mt < 4; mt++)
        #pragma unroll
        for (int nt = 0; nt < 4; nt++) {
            int n = n0 + wn*32 + nt*8 + 2*t4;
            float2 bi = *(const float2*)&bias[n];
            int m = m0 + wm*64 + mt*16 + g;
            *(float2*)&out[(size_t)m * CH + n] =
                make_float2(c[mt][nt][0] + bi.x, c[mt][nt][1] + bi.y);
            *(float2*)&out[(size_t)(m + 8) * CH + n] =
                make_float2(c[mt][nt][2] + bi.x, c[mt][nt][3] + bi.y);
        }
}

// ---------------------------------------------------------------------------
extern "C" void kernel_launch(void* const* d_in, const int* in_sizes, int n_in,
                              void* d_out, int out_size)
{
    const float* x      = (const float*)d_in[0];
    const float* w_qkv  = (const float*)d_in[1];
    const float* w_proj = (const float*)d_in[2];
    const float* b_proj = (const float*)d_in[3];

    float* out  = (float*)d_out;
    float* attn = out + (size_t)MROWS * CH;

    bf16 *wq_h, *wq_l, *wp_h, *wp_l;
    cudaGetSymbolAddress((void**)&wq_h, g_wq_h);
    cudaGetSymbolAddress((void**)&wq_l, g_wq_l);
    cudaGetSymbolAddress((void**)&wp_h, g_wp_h);
    cudaGetSymbolAddress((void**)&wp_l, g_wp_l);

    // 0. prep
    k_tx<<<MROWS*CH/1024, 256>>>(x);
    k_tw<<<dim3(3*CH/32, CH/32), dim3(32, 8)>>>(w_qkv, wq_h, wq_l, CH, 3*CH);
    k_tw<<<dim3(CH/32,   CH/32), dim3(32, 8)>>>(w_proj, wp_h, wp_l, CH, CH);

    // 1. QKV projection (pipelined)
    k_qkv<<<dim3(3*CH/128, MROWS/128), 256>>>();

    // 2. raw scores + softmax partials
    k_scores<<<dim3(SEQ/128, SEQ/128, BHNUM), 256>>>(attn);

    // 3. per-row softmax stats
    k_red<<<BHNUM*SEQ/256, 256>>>();

    // 4. normalize + P write + ctx = P@V
    k_ctx<<<dim3(SEQ/128, BHNUM), 256>>>(attn);

    // 5. output projection + bias (pipelined)
    k_proj<<<dim3(CH/128, MROWS/128), 256>>>(b_proj, out);
}